// round 4
// baseline (speedup 1.0000x reference)
#include <cuda_runtime.h>
#include <cuda_bf16.h>

// Problem: x [32, 512, 512] f32 -> pad 128 each side -> [32, 768, 768]
//          -> nearest-neighbor upsample x4 both dims -> out [32, 3072, 3072] f32.
//
// out[b][i][j] = (512 <= i < 2560 && 512 <= j < 2560)
//               ? x[b][(i-512)/4][(j-512)/4] : 0
//
// Layout exploit: SCALE=4 == float4 width, PAD*SCALE=512 is 16-float aligned.
// Each thread writes one 64B group (4 float4) of a single output row; the
// group is either entirely zero (pad) or fed by ONE aligned float4 input load
// (4 consecutive input cols -> 4 broadcast float4 stores).

#define OUT_W      3072
#define OUT_H      3072
#define BATCH      32
#define GROUPS_PER_ROW 192          // 3072 floats / 16 floats per group
#define TOTAL_ROWS (BATCH * OUT_H)  // 98304

__global__ __launch_bounds__(256) void scale_layer_kernel(
    const float* __restrict__ x, float4* __restrict__ out)
{
    unsigned int idx = blockIdx.x * 256u + threadIdx.x;   // group index
    // exact launch: TOTAL_ROWS * GROUPS_PER_ROW / 256 blocks, no tail

    unsigned int row = idx / GROUPS_PER_ROW;   // 0 .. 98303
    unsigned int g   = idx % GROUPS_PER_ROW;   // 0 .. 191

    unsigned int b = row / OUT_H;              // batch
    unsigned int i = row % OUT_H;              // output row within image

    float4 v0, v1, v2, v3;

    // interior rows: i in [512, 2560); interior groups: g in [32, 160)
    if ((i - 512u) < 2048u && (g - 32u) < 128u) {
        unsigned int ii = (i - 512u) >> 2;       // input row 0..511
        unsigned int jj = (g - 32u) << 2;        // input col base 0..508, %4==0
        const float4 in = *reinterpret_cast<const float4*>(
            x + ((size_t)b * 512u + ii) * 512u + jj);
        v0 = make_float4(in.x, in.x, in.x, in.x);
        v1 = make_float4(in.y, in.y, in.y, in.y);
        v2 = make_float4(in.z, in.z, in.z, in.z);
        v3 = make_float4(in.w, in.w, in.w, in.w);
    } else {
        v0 = v1 = v2 = v3 = make_float4(0.f, 0.f, 0.f, 0.f);
    }

    float4* o = out + (size_t)idx * 4u;  // group idx * 4 float4 = 64B
    o[0] = v0;
    o[1] = v1;
    o[2] = v2;
    o[3] = v3;
}

extern "C" void kernel_launch(void* const* d_in, const int* in_sizes, int n_in,
                              void* d_out, int out_size)
{
    const float* x = (const float*)d_in[0];
    float4* out = (float4*)d_out;

    // total groups = 98304 * 192 = 18,874,368 ; / 256 = 73,728 blocks exactly
    const unsigned int n_groups = (unsigned int)TOTAL_ROWS * GROUPS_PER_ROW;
    dim3 grid(n_groups / 256u);
    scale_layer_kernel<<<grid, 256>>>(x, out);
}